// round 7
// baseline (speedup 1.0000x reference)
#include <cuda_runtime.h>
#include <cstdint>

// Problem constants
#define KV_LEN      4096
#define PAGE_SZ     16
#define BSZ         4
#define SEQ         512
#define HEADS       16
#define HDIM        128
#define PAGES       1024
#define PPS         256
#define SHIFT_PAGES 33
#define FIRST_NEW_PAGE 223
#define LAST_PAGE   255

// float4 geometry
#define HALF_F4  8192
#define PAGE_F4  16384
#define SLOT_F4  512
#define HEAD_F4  32
#define CHUNK_F4 2048

#define NTASKS   8192
#define GRID_P   888      // 148 SMs * 6 CTAs

// log2(10000)/64
#define LOG2_THETA_OVER_64 0.2076205059304601486

__device__ unsigned int g_task_counter;

__global__ void reset_counter_kernel() { g_task_counter = 0u; }

// Persistent kernel; task decomposition unchanged:
//   kv = t&1, chunk = (t>>1)&3, logical page i = t>>3
__global__ __launch_bounds__(256, 6) void kv_rotate_kernel(
    const float* __restrict__ knew,
    const float* __restrict__ vnew,
    const float* __restrict__ cache,
    const int*   __restrict__ pidx,
    float*       __restrict__ out)
{
    const int tid = threadIdx.x;
    // 16-byte alignment is REQUIRED: rope path reads these via float4 casts.
    __shared__ __align__(16) float s_cos[4][64];
    __shared__ __align__(16) float s_sin[4][64];
    __shared__ int s_task;

    // per-thread trig-table coordinates (4 slots * 64 freqs = 256 = blockDim)
    const int slotf = tid >> 6;
    const int f     = tid & 63;
    const float invf = (float)exp2(-(double)f * LOG2_THETA_OVER_64);

    int t = blockIdx.x;   // first task static
    while (t < NTASKS) {
        const int kv    = t & 1;
        const int chunk = (t >> 1) & 3;
        const int i     = t >> 3;
        const int b     = i >> 8;
        const int p     = i & 255;

        const int dpage = __ldg(&pidx[i]);
        float4* dst = (float4*)out + (size_t)dpage * PAGE_F4 + kv * HALF_F4 + chunk * CHUNK_F4;

        // source selection (page-granular: SHIFT+SEQ = 33 pages)
        const float4* src;
        if (p < FIRST_NEW_PAGE) {
            const int spage = __ldg(&pidx[b * PPS + p + SHIFT_PAGES]);
            src = (const float4*)cache + (size_t)spage * PAGE_F4 + kv * HALF_F4 + chunk * CHUNK_F4;
        } else if (p == LAST_PAGE) {
            src = (const float4*)cache + (size_t)dpage * PAGE_F4 + kv * HALF_F4 + chunk * CHUNK_F4;
        } else {
            const float* base = kv ? vnew : knew;
            src = (const float4*)base
                + (size_t)(b * SEQ + (p - FIRST_NEW_PAGE) * PAGE_SZ) * SLOT_F4 + chunk * CHUNK_F4;
        }

        if (kv == 1) {
            // streaming copy: 2048 f4, front-batched MLP=8
            float4 r[8];
            #pragma unroll
            for (int j = 0; j < 8; j++) r[j] = __ldcs(&src[tid + 256 * j]);
            #pragma unroll
            for (int j = 0; j < 8; j++) __stcs(&dst[tid + 256 * j], r[j]);
        } else {
            // k quarter: rotate-half RoPE on 4 slots
            const float ang = (float)(p * PAGE_SZ + chunk * 4 + slotf) * invf;
            float sv, cv;
            sincosf(ang, &sv, &cv);
            s_cos[slotf][f] = cv;
            s_sin[slotf][f] = sv;
            __syncthreads();

            const int h = tid >> 4;
            const int j = tid & 15;
            const int lane_off = h * HEAD_F4 + j;

            #pragma unroll
            for (int sp2 = 0; sp2 < 2; sp2++) {
                const int s0 = sp2 * 2;
                float4 a[2], bb[2];
                #pragma unroll
                for (int q = 0; q < 2; q++) {
                    const float4* sp = src + (s0 + q) * SLOT_F4 + lane_off;
                    a[q]  = __ldcs(&sp[0]);    // x1
                    bb[q] = __ldcs(&sp[16]);   // x2
                }
                #pragma unroll
                for (int q = 0; q < 2; q++) {
                    const float4 c = *(const float4*)&s_cos[s0 + q][4 * j];
                    const float4 s = *(const float4*)&s_sin[s0 + q][4 * j];
                    float4 o1, o2;
                    o1.x = a[q].x * c.x - bb[q].x * s.x;  o2.x = a[q].x * s.x + bb[q].x * c.x;
                    o1.y = a[q].y * c.y - bb[q].y * s.y;  o2.y = a[q].y * s.y + bb[q].y * c.y;
                    o1.z = a[q].z * c.z - bb[q].z * s.z;  o2.z = a[q].z * s.z + bb[q].z * c.z;
                    o1.w = a[q].w * c.w - bb[q].w * s.w;  o2.w = a[q].w * s.w + bb[q].w * c.w;

                    float4* dp = dst + (s0 + q) * SLOT_F4 + lane_off;
                    __stcs(&dp[0],  o1);
                    __stcs(&dp[16], o2);
                }
            }
        }

        // dynamic next task: pool starts after the GRID_P static tasks
        if (tid == 0) s_task = (int)(GRID_P + atomicAdd(&g_task_counter, 1u));
        __syncthreads();          // publish s_task; also fences s_cos/s_sin reuse
        t = s_task;
        __syncthreads();          // all threads read t before tid0 may overwrite
    }
}

extern "C" void kernel_launch(void* const* d_in, const int* in_sizes, int n_in,
                              void* d_out, int out_size) {
    const float* k     = (const float*)d_in[0];
    const float* v     = (const float*)d_in[1];
    const float* cache = (const float*)d_in[2];
    const int*   pidx  = (const int*)d_in[3];
    float*       out   = (float*)d_out;

    reset_counter_kernel<<<1, 1>>>();
    kv_rotate_kernel<<<GRID_P, 256>>>(k, v, cache, pidx, out);
}

// round 8
// speedup vs baseline: 1.0564x; 1.0564x over previous
#include <cuda_runtime.h>
#include <cstdint>

// Problem constants
#define KV_LEN      4096
#define PAGE_SZ     16
#define BSZ         4
#define SEQ         512
#define HEADS       16
#define HDIM        128
#define PAGES       1024
#define PPS         256
#define SHIFT_PAGES 33
#define FIRST_NEW_PAGE 223
#define LAST_PAGE   255

// float4 geometry
#define HALF_F4  8192       // one kv half of a page
#define PAGE_F4  16384
#define SLOT_F4  512        // one token: 16*128/4
#define HEAD_F4  32
#define CHUNK_F4 1024       // eighth of a half: 2 slots (16 KB)

// log2(10000)/64
#define LOG2_THETA_OVER_64 0.2076205059304601486

// Task decomposition: 16384 tasks of 16KB each.
//   kv    = t & 1        (interleave rope/copy across SMs)
//   chunk = (t>>1) & 7   (eighth within the half: 2 slots)
//   i     = t >> 4       (logical page 0..1023)
__global__ __launch_bounds__(256, 8) void kv_rotate_kernel(
    const float* __restrict__ knew,
    const float* __restrict__ vnew,
    const float* __restrict__ cache,
    const int*   __restrict__ pidx,
    float*       __restrict__ out)
{
    const int t     = blockIdx.x;
    const int kv    = t & 1;
    const int chunk = (t >> 1) & 7;
    const int i     = t >> 4;
    const int b     = i >> 8;
    const int p     = i & 255;
    const int tid   = threadIdx.x;

    const int dpage = __ldg(&pidx[i]);
    float4* dst = (float4*)out + (size_t)dpage * PAGE_F4 + kv * HALF_F4 + chunk * CHUNK_F4;

    // source selection (page-granular: SHIFT+SEQ = 33 pages)
    const float4* src;
    if (p < FIRST_NEW_PAGE) {
        const int spage = __ldg(&pidx[b * PPS + p + SHIFT_PAGES]);
        src = (const float4*)cache + (size_t)spage * PAGE_F4 + kv * HALF_F4 + chunk * CHUNK_F4;
    } else if (p == LAST_PAGE) {
        src = (const float4*)cache + (size_t)dpage * PAGE_F4 + kv * HALF_F4 + chunk * CHUNK_F4;
    } else {
        const float* base = kv ? vnew : knew;
        src = (const float4*)base
            + (size_t)(b * SEQ + (p - FIRST_NEW_PAGE) * PAGE_SZ) * SLOT_F4 + chunk * CHUNK_F4;
    }

    if (kv == 1) {
        // pure streaming copy: 1024 f4, front-batched MLP=4
        float4 r[4];
        #pragma unroll
        for (int j = 0; j < 4; j++) r[j] = __ldcs(&src[tid + 256 * j]);
        #pragma unroll
        for (int j = 0; j < 4; j++) __stcs(&dst[tid + 256 * j], r[j]);
        return;
    }

    // ---- k chunk: rotate-half RoPE on 2 slots ----
    __shared__ __align__(16) float s_cos[2][64];
    __shared__ __align__(16) float s_sin[2][64];

    if (tid < 128) {
        // 2 slots * 64 freqs = 128 entries
        const int slot = tid >> 6;
        const int f    = tid & 63;
        const float invf = (float)exp2(-(double)f * LOG2_THETA_OVER_64);  // f32-rounded inv_freq
        const float ang  = (float)(p * PAGE_SZ + chunk * 2 + slot) * invf;
        float s, c;
        sincosf(ang, &s, &c);
        s_cos[slot][f] = c;
        s_sin[slot][f] = s;
    }
    __syncthreads();

    // 2 slots * (16 heads * 16 j) = 512 units, 2 per thread
    const int h = tid >> 4;
    const int j = tid & 15;
    const int lane_off = h * HEAD_F4 + j;

    float4 a[2], bb[2];
    #pragma unroll
    for (int q = 0; q < 2; q++) {
        const float4* sp = src + q * SLOT_F4 + lane_off;
        a[q]  = __ldcs(&sp[0]);    // x1 (dims 4j..4j+3)
        bb[q] = __ldcs(&sp[16]);   // x2 (dims 64+4j..)
    }
    #pragma unroll
    for (int q = 0; q < 2; q++) {
        const float4 c = *(const float4*)&s_cos[q][4 * j];
        const float4 s = *(const float4*)&s_sin[q][4 * j];
        float4 o1, o2;
        o1.x = a[q].x * c.x - bb[q].x * s.x;  o2.x = a[q].x * s.x + bb[q].x * c.x;
        o1.y = a[q].y * c.y - bb[q].y * s.y;  o2.y = a[q].y * s.y + bb[q].y * c.y;
        o1.z = a[q].z * c.z - bb[q].z * s.z;  o2.z = a[q].z * s.z + bb[q].z * c.z;
        o1.w = a[q].w * c.w - bb[q].w * s.w;  o2.w = a[q].w * s.w + bb[q].w * c.w;

        float4* dp = dst + q * SLOT_F4 + lane_off;
        __stcs(&dp[0],  o1);
        __stcs(&dp[16], o2);
    }
}

extern "C" void kernel_launch(void* const* d_in, const int* in_sizes, int n_in,
                              void* d_out, int out_size) {
    const float* k     = (const float*)d_in[0];
    const float* v     = (const float*)d_in[1];
    const float* cache = (const float*)d_in[2];
    const int*   pidx  = (const int*)d_in[3];
    float*       out   = (float*)d_out;

    kv_rotate_kernel<<<PAGES * 16, 256>>>(k, v, cache, pidx, out);
}

// round 9
// speedup vs baseline: 1.0736x; 1.0163x over previous
#include <cuda_runtime.h>
#include <cstdint>

// Problem constants
#define KV_LEN      4096
#define PAGE_SZ     16
#define BSZ         4
#define SEQ         512
#define HEADS       16
#define HDIM        128
#define PAGES       1024
#define PPS         256
#define SHIFT_PAGES 33
#define FIRST_NEW_PAGE 223
#define LAST_PAGE   255

// float4 geometry
#define HALF_F4  8192       // one kv half of a page
#define PAGE_F4  16384
#define SLOT_F4  512        // one token: 16*128/4
#define HEAD_F4  32
#define CHUNK_F4 1024       // eighth of a half: 2 slots (16 KB)

// log2(10000)/64
#define LOG2_THETA_OVER_64 0.2076205059304601486

// 16384 tasks of 16KB, 128-thread blocks, per-thread MLP=8.
//   kv    = t & 1
//   chunk = (t>>1) & 7   (eighth of a half: 2 slots)
//   i     = t >> 4       (logical page 0..1023)
__global__ __launch_bounds__(128, 10) void kv_rotate_kernel(
    const float* __restrict__ knew,
    const float* __restrict__ vnew,
    const float* __restrict__ cache,
    const int*   __restrict__ pidx,
    float*       __restrict__ out)
{
    const int t     = blockIdx.x;
    const int kv    = t & 1;
    const int chunk = (t >> 1) & 7;
    const int i     = t >> 4;
    const int b     = i >> 8;
    const int p     = i & 255;
    const int tid   = threadIdx.x;

    const int dpage = __ldg(&pidx[i]);
    float4* dst = (float4*)out + (size_t)dpage * PAGE_F4 + kv * HALF_F4 + chunk * CHUNK_F4;

    // source selection (page-granular: SHIFT+SEQ = 33 pages)
    const float4* src;
    if (p < FIRST_NEW_PAGE) {
        const int spage = __ldg(&pidx[b * PPS + p + SHIFT_PAGES]);
        src = (const float4*)cache + (size_t)spage * PAGE_F4 + kv * HALF_F4 + chunk * CHUNK_F4;
    } else if (p == LAST_PAGE) {
        src = (const float4*)cache + (size_t)dpage * PAGE_F4 + kv * HALF_F4 + chunk * CHUNK_F4;
    } else {
        const float* base = kv ? vnew : knew;
        src = (const float4*)base
            + (size_t)(b * SEQ + (p - FIRST_NEW_PAGE) * PAGE_SZ) * SLOT_F4 + chunk * CHUNK_F4;
    }

    if (kv == 1) {
        // streaming copy: 1024 f4 by 128 threads, front-batched MLP=8
        float4 r[8];
        #pragma unroll
        for (int j = 0; j < 8; j++) r[j] = __ldcs(&src[tid + 128 * j]);
        #pragma unroll
        for (int j = 0; j < 8; j++) __stcs(&dst[tid + 128 * j], r[j]);
        return;
    }

    // ---- k chunk: rotate-half RoPE on 2 slots ----
    __shared__ __align__(16) float s_cos[2][64];
    __shared__ __align__(16) float s_sin[2][64];

    {
        // 2 slots * 64 freqs = 128 entries = exactly one per thread
        const int slot = tid >> 6;
        const int f    = tid & 63;
        const float invf = (float)exp2(-(double)f * LOG2_THETA_OVER_64);  // f32-rounded inv_freq
        const float ang  = (float)(p * PAGE_SZ + chunk * 2 + slot) * invf;
        float s, c;
        sincosf(ang, &s, &c);
        s_cos[slot][f] = c;
        s_sin[slot][f] = s;
    }
    __syncthreads();

    // 2 slots * 16 heads * 16 j = 512 units; thread owns heads {h0, h0+8} for its j.
    const int h0 = tid >> 4;          // 0..7
    const int j  = tid & 15;

    // front-batch all 8 loads (MLP=8)
    float4 a[2][2], bb[2][2];
    #pragma unroll
    for (int q = 0; q < 2; q++) {         // slot
        #pragma unroll
        for (int e = 0; e < 2; e++) {     // head group
            const float4* sp = src + q * SLOT_F4 + (h0 + 8 * e) * HEAD_F4 + j;
            a[q][e]  = __ldcs(&sp[0]);    // x1 (dims 4j..4j+3)
            bb[q][e] = __ldcs(&sp[16]);   // x2 (dims 64+4j..)
        }
    }

    #pragma unroll
    for (int q = 0; q < 2; q++) {
        const float4 c = *(const float4*)&s_cos[q][4 * j];
        const float4 s = *(const float4*)&s_sin[q][4 * j];
        #pragma unroll
        for (int e = 0; e < 2; e++) {
            float4 o1, o2;
            o1.x = a[q][e].x * c.x - bb[q][e].x * s.x;  o2.x = a[q][e].x * s.x + bb[q][e].x * c.x;
            o1.y = a[q][e].y * c.y - bb[q][e].y * s.y;  o2.y = a[q][e].y * s.y + bb[q][e].y * c.y;
            o1.z = a[q][e].z * c.z - bb[q][e].z * s.z;  o2.z = a[q][e].z * s.z + bb[q][e].z * c.z;
            o1.w = a[q][e].w * c.w - bb[q][e].w * s.w;  o2.w = a[q][e].w * s.w + bb[q][e].w * c.w;

            float4* dp = dst + q * SLOT_F4 + (h0 + 8 * e) * HEAD_F4 + j;
            __stcs(&dp[0],  o1);
            __stcs(&dp[16], o2);
        }
    }
}

extern "C" void kernel_launch(void* const* d_in, const int* in_sizes, int n_in,
                              void* d_out, int out_size) {
    const float* k     = (const float*)d_in[0];
    const float* v     = (const float*)d_in[1];
    const float* cache = (const float*)d_in[2];
    const int*   pidx  = (const int*)d_in[3];
    float*       out   = (float*)d_out;

    kv_rotate_kernel<<<PAGES * 16, 128>>>(k, v, cache, pidx, out);
}